// round 11
// baseline (speedup 1.0000x reference)
#include <cuda_runtime.h>
#include <cuda_fp16.h>
#include <cstdint>

// ---------------------------------------------------------------------------
// Problem constants
// ---------------------------------------------------------------------------
#define NROWS_MAX 100000
#define CONCAT    352
#define NODE_DIM  128
#define EQUI_DIM  480
#define OUT_DIM   608

// Packed weights: 22 slots (11 W1 + 11 W2); slot = 32 k-rows x 360 fp16
// (row stride 720 B, n-contiguous) = 23040 B.
__device__ __half g_wpad[(size_t)22 * 32 * 360];

// ---------------------------------------------------------------------------
// PTX helpers (sm_90-era baseline only; tcgen05 rejected by this toolchain)
// ---------------------------------------------------------------------------
__device__ __forceinline__ uint32_t smem_to_u32(const void* p) {
    uint32_t a;
    asm("{ .reg .u64 t; cvta.to.shared.u64 t, %1; cvt.u32.u64 %0, t; }" : "=r"(a) : "l"(p));
    return a;
}

__device__ __forceinline__ void mma_fp16(float* d, const uint32_t* a, uint32_t b0, uint32_t b1) {
    asm volatile(
        "mma.sync.aligned.m16n8k16.row.col.f32.f16.f16.f32 "
        "{%0,%1,%2,%3}, {%4,%5,%6,%7}, {%8,%9}, {%0,%1,%2,%3};\n"
        : "+f"(d[0]), "+f"(d[1]), "+f"(d[2]), "+f"(d[3])
        : "r"(a[0]), "r"(a[1]), "r"(a[2]), "r"(a[3]), "r"(b0), "r"(b1));
}

__device__ __forceinline__ void ldsm_a4(uint32_t* r, uint32_t addr) {
    asm volatile("ldmatrix.sync.aligned.m8n8.x4.shared.b16 {%0,%1,%2,%3}, [%4];"
        : "=r"(r[0]), "=r"(r[1]), "=r"(r[2]), "=r"(r[3]) : "r"(addr));
}
__device__ __forceinline__ void ldsm_bt4(uint32_t* r, uint32_t addr) {
    asm volatile("ldmatrix.sync.aligned.m8n8.x4.trans.shared.b16 {%0,%1,%2,%3}, [%4];"
        : "=r"(r[0]), "=r"(r[1]), "=r"(r[2]), "=r"(r[3]) : "r"(addr));
}
__device__ __forceinline__ void ldsm_bt2(uint32_t& r0, uint32_t& r1, uint32_t addr) {
    asm volatile("ldmatrix.sync.aligned.m8n8.x2.trans.shared.b16 {%0,%1}, [%2];"
        : "=r"(r0), "=r"(r1) : "r"(addr));
}

#define MBARRIER_INIT(addr, cnt) \
    asm volatile("mbarrier.init.shared.b64 [%0], %1;" :: "r"((uint32_t)(addr)), "r"((uint32_t)(cnt)) : "memory")

#define MBARRIER_EXPECT_TX(addr, bytes) \
    asm volatile("mbarrier.arrive.expect_tx.shared.b64 _, [%0], %1;" \
                 :: "r"((uint32_t)(addr)), "r"((uint32_t)(bytes)) : "memory")

#define MBARRIER_ARRIVE(addr) \
    asm volatile("mbarrier.arrive.shared.b64 _, [%0];" :: "r"((uint32_t)(addr)) : "memory")

#define BULK_G2S(dst, src, bytes, mbar) \
    asm volatile("cp.async.bulk.shared::cluster.global.mbarrier::complete_tx::bytes [%0], [%1], %2, [%3];" \
                 :: "r"((uint32_t)(dst)), "l"(src), "r"((uint32_t)(bytes)), "r"((uint32_t)(mbar)) : "memory")

#define MBARRIER_WAIT_PARITY(mbar_smem_addr, phase_parity) do { \
    uint32_t _mbar = (uint32_t)(mbar_smem_addr); \
    uint32_t _parity = (uint32_t)(phase_parity); \
    uint32_t _done; \
    asm volatile( \
        "{\n\t.reg .pred p;\n\t" \
        "mbarrier.try_wait.parity.acquire.cta.shared::cta.b64 p, [%1], %2;\n\t" \
        "selp.b32 %0, 1, 0, p;\n\t}" \
        : "=r"(_done) : "r"(_mbar), "r"(_parity) : "memory"); \
    if (!_done) { \
        asm volatile( \
            "{\n\t.reg .pred P1;\n\t" \
            "WAIT_LOOP_%=:\n\t" \
            "mbarrier.try_wait.parity.acquire.cta.shared::cta.b64 P1, [%0], %1, 0x989680;\n\t" \
            "@P1 bra.uni WAIT_DONE_%=;\n\t" \
            "bra.uni WAIT_LOOP_%=;\n\t" \
            "WAIT_DONE_%=:\n\t}" \
            :: "r"(_mbar), "r"(_parity) : "memory"); \
    } \
} while(0)

// ---------------------------------------------------------------------------
// Kernel 0: pack W1/W2 -> g_wpad as plain fp16 rows [k][n], stride 360 halves.
// 176 blocks: slot j = b/8, part p = b%8 (4 k-rows per block).
// ---------------------------------------------------------------------------
__global__ void pack_kernel(const float* __restrict__ W1, const float* __restrict__ W2) {
    int b = blockIdx.x;
    int j = b >> 3, p = b & 7;
    const float* src = (j < 11) ? (W1 + (size_t)j * 32 * CONCAT)
                                : (W2 + (size_t)(j - 11) * 32 * CONCAT);
    __half* dst = g_wpad + (size_t)j * 32 * 360;
    for (int i = threadIdx.x; i < 4 * CONCAT; i += 256) {
        int k = p * 4 + i / CONCAT, n = i % CONCAT;
        dst[k * 360 + n] = __float2half_rn(src[(size_t)k * CONCAT + n]);
    }
}

// ---------------------------------------------------------------------------
// Fused kernel: norm prologue + MLP + gated epilogue.
// 64-row CTAs, 256 threads (8 warps, 2M x 4N, warp tile 32x88), 2 CTAs/SM.
// A (64x352 fp16, row stride 720 B) built in smem by the norm prologue;
// B streamed as K=32 slots via 2-deep bulk ring with full/free mbarriers.
// All MMA operand loads via ldmatrix.
//
// smem bytes:
//   bias  @0     : 704 f32             (2816)
//   stats @2816  : 64*4 f32            (1024)  -> 3840
//   A     @3840  : 64*180 words        (46080) -> 49920
//   ring  @49920 : 2*32*360 halves     (46080) -> 96000
//   mbars @96000 : full0,full1,free0,free1    -> 96032
//   G overlay @3840 : 64*356 f32       (91136) -> 94976 (post-loop, safe)
// total 96032 B/CTA -> 2 CTAs/SM
// ---------------------------------------------------------------------------
#define SM_STATS_F 704
#define SM_A_B     3840
#define SM_RING_B  49920
#define SM_MBAR    96000
#define SMEM_TOTAL 96032
#define B_SLOT_B   23040
#define SM_G_F     960          // float index of G overlay (3840/4)

__global__ __launch_bounds__(256, 2) void mlp_kernel(
    const float* __restrict__ b1, const float* __restrict__ b2,
    const float* __restrict__ lnw, const float* __restrict__ lnb,
    const float* __restrict__ nsc, const float* __restrict__ neq,
    float* __restrict__ out, int N)
{
    extern __shared__ char smc[];
    float* smf = (float*)smc;
    uint32_t sb = smem_to_u32(smc);
    const int tid = threadIdx.x, lane = tid & 31, wid = tid >> 5;
    const int wm = wid >> 2, wn = wid & 3;          // 2 x 4 warp grid
    const int q = lane >> 2, kq = lane & 3;
    const int rowBase = blockIdx.x * 64;

    uint32_t* Aw = (uint32_t*)(smc + SM_A_B);

    if (tid == 0) {
        MBARRIER_INIT(sb + SM_MBAR + 0, 1);   // full0
        MBARRIER_INIT(sb + SM_MBAR + 8, 1);   // full1
        MBARRIER_INIT(sb + SM_MBAR + 16, 8);  // free0 (one arrive per warp)
        MBARRIER_INIT(sb + SM_MBAR + 24, 8);  // free1
    }
    for (int i = tid; i < 704; i += 256)
        smf[i] = (i < CONCAT) ? b1[i] : b2[i - CONCAT];
    __syncthreads();

    // producer: prefetch B slots 0,1
    if (tid == 0) {
#pragma unroll
        for (int s = 0; s < 2; ++s) {
            MBARRIER_EXPECT_TX(sb + SM_MBAR + 8 * s, B_SLOT_B);
            BULK_G2S(sb + SM_RING_B + s * B_SLOT_B, g_wpad + (size_t)s * 11520,
                     B_SLOT_B, sb + SM_MBAR + 8 * s);
        }
    }

    // ---------------- norm prologue: 8 rows per warp ----------------
    {
        const float4 lw4 = *(const float4*)&lnw[lane * 4];
        const float4 lb4 = *(const float4*)&lnb[lane * 4];
#pragma unroll 1
        for (int pass = 0; pass < 8; ++pass) {
            int rr = wid * 8 + pass;
            int gr = rowBase + rr;
            float4 xv = make_float4(0.f, 0.f, 0.f, 0.f);
            float4 ev = make_float4(0.f, 0.f, 0.f, 0.f);
            float a0 = 0.f, a1 = 0.f, a2 = 0.f, a3 = 0.f, a4 = 0.f, a5 = 0.f;
            float q0 = 0.f, q1 = 0.f, q2 = 0.f, q3 = 0.f, q4 = 0.f;
            if (gr < N) {
                const float* xs = nsc + (size_t)gr * NODE_DIM;
                const float* xe = neq + (size_t)gr * EQUI_DIM;
                xv = *(const float4*)&xs[lane * 4];
                ev = *(const float4*)&xe[lane * 4];
                const float* l1p = &xe[128 + 6 * lane];
                a0 = l1p[0]; a1 = l1p[1]; a2 = l1p[2];
                a3 = l1p[3]; a4 = l1p[4]; a5 = l1p[5];
                const float* l2p = &xe[320 + 5 * lane];
                q0 = l2p[0]; q1 = l2p[1]; q2 = l2p[2]; q3 = l2p[3]; q4 = l2p[4];
            }
            float s1a = a0 * a0 + a1 * a1 + a2 * a2;
            float s1b = a3 * a3 + a4 * a4 + a5 * a5;
            float s2  = q0 * q0 + q1 * q1 + q2 * q2 + q3 * q3 + q4 * q4;

            float sx  = xv.x + xv.y + xv.z + xv.w;
            float sxx = xv.x * xv.x + xv.y * xv.y + xv.z * xv.z + xv.w * xv.w;
            float se  = ev.x + ev.y + ev.z + ev.w;
            float se2 = ev.x * ev.x + ev.y * ev.y + ev.z * ev.z + ev.w * ev.w;
            float ssl1 = s1a + s1b;
            float ssl2 = s2;
#pragma unroll
            for (int o = 16; o > 0; o >>= 1) {
                sx   += __shfl_xor_sync(~0u, sx, o);
                sxx  += __shfl_xor_sync(~0u, sxx, o);
                se   += __shfl_xor_sync(~0u, se, o);
                se2  += __shfl_xor_sync(~0u, se2, o);
                ssl1 += __shfl_xor_sync(~0u, ssl1, o);
                ssl2 += __shfl_xor_sync(~0u, ssl2, o);
            }
            float mu  = sx * (1.f / 128.f);
            float var = sxx * (1.f / 128.f) - mu * mu;
            float rs  = rsqrtf(var + 1e-5f);
            float m0  = se * (1.f / 128.f);
            float sc2m = se2 * (1.f / 128.f) - m0 * m0;
            float r0 = rsqrtf(sc2m + 1e-5f);
            float r1 = rsqrtf(ssl1 * (1.f / 64.f) + 1e-5f);
            float r2 = rsqrtf(ssl2 * (1.f / 32.f) + 1e-5f);

            uint32_t* Arow = Aw + rr * 180;
            {
                float f0 = (xv.x - mu) * rs * lw4.x + lb4.x;
                float f1 = (xv.y - mu) * rs * lw4.y + lb4.y;
                float f2 = (xv.z - mu) * rs * lw4.z + lb4.z;
                float f3 = (xv.w - mu) * rs * lw4.w + lb4.w;
                __half2 p0 = __floats2half2_rn(f0, f1);
                __half2 p1 = __floats2half2_rn(f2, f3);
                Arow[lane * 2] = *(uint32_t*)&p0;
                Arow[lane * 2 + 1] = *(uint32_t*)&p1;
            }
            {
                float g0 = (ev.x - m0) * r0, g1 = (ev.y - m0) * r0;
                float g2 = (ev.z - m0) * r0, g3 = (ev.w - m0) * r0;
                __half2 p0 = __floats2half2_rn(g0 * g0, g1 * g1);
                __half2 p1 = __floats2half2_rn(g2 * g2, g3 * g3);
                Arow[64 + lane * 2] = *(uint32_t*)&p0;
                Arow[64 + lane * 2 + 1] = *(uint32_t*)&p1;
            }
            {
                float v0 = s1a * r1 * r1 * 0.57735026918962576451f;
                float v1 = s1b * r1 * r1 * 0.57735026918962576451f;
                __half2 p = __floats2half2_rn(v0, v1);
                Arow[128 + lane] = *(uint32_t*)&p;
            }
            {
                float v = s2 * r2 * r2 * 0.44721359549995793928f;
                float vhi = __shfl_down_sync(~0u, v, 1);
                if (!(lane & 1)) {
                    __half2 p = __floats2half2_rn(v, vhi);
                    Arow[160 + (lane >> 1)] = *(uint32_t*)&p;
                }
            }
            if (lane == 0)
                *(float4*)&smf[SM_STATS_F + rr * 4] = make_float4(m0, r0, r1, r2);
        }
    }
    __syncthreads();   // A tile + stats complete

    float acc[2][11][4];
#pragma unroll
    for (int mt = 0; mt < 2; mt++)
#pragma unroll
        for (int nt = 0; nt < 11; nt++)
#pragma unroll
            for (int e = 0; e < 4; e++) acc[mt][nt][e] = 0.f;

    // ldmatrix lane addresses (g = lane/8, l8 = lane%8)
    const int g8 = lane >> 3, l8 = lane & 7;
    // A: row = wm*32 + mt*16 + (g8&1)*8 + l8 ; col byte = kByte + (g8>>1)*16
    const uint32_t aLane = sb + SM_A_B +
        (uint32_t)((wm * 32 + (g8 & 1) * 8 + l8) * 720 + (g8 >> 1) * 16);
    // B: row k = ks*16 + (g8&1)*8 + l8 ; col byte = wn*176 + pair*32 + (g8>>1)*16
    const uint32_t bLane = (uint32_t)(((g8 & 1) * 8 + l8) * 720 + (g8 >> 1) * 16 + wn * 176);
    const uint32_t bLaneX2 = (uint32_t)(((g8 & 1) * 8 + l8) * 720 + wn * 176 + 160);

    // 22 iterations of K=32: 0..10 = GEMM1 (W1), 11..21 = GEMM2 (W2)
#pragma unroll 1
    for (int it = 0; it < 22; ++it) {
        const int slot = it & 1;
        MBARRIER_WAIT_PARITY(sb + SM_MBAR + 8 * slot, (it >> 1) & 1);

        if (it == 11) {
            // epilogue 1: H = fp16(silu(D1 + b1)) overwrites A in place.
            __syncthreads();   // all warps done reading A for GEMM1
#pragma unroll
            for (int mt = 0; mt < 2; mt++) {
                int r0 = wm * 32 + mt * 16 + q;
#pragma unroll
                for (int nt = 0; nt < 11; nt++) {
                    int c = wn * 88 + nt * 8 + 2 * kq;
                    int c2 = c >> 1;
                    float h0 = acc[mt][nt][0] + smf[c];
                    float h1 = acc[mt][nt][1] + smf[c + 1];
                    float h2 = acc[mt][nt][2] + smf[c];
                    float h3 = acc[mt][nt][3] + smf[c + 1];
                    h0 = __fdividef(h0, 1.f + __expf(-h0));
                    h1 = __fdividef(h1, 1.f + __expf(-h1));
                    h2 = __fdividef(h2, 1.f + __expf(-h2));
                    h3 = __fdividef(h3, 1.f + __expf(-h3));
                    __half2 p01 = __floats2half2_rn(h0, h1);
                    __half2 p23 = __floats2half2_rn(h2, h3);
                    Aw[r0 * 180 + c2] = *(uint32_t*)&p01;
                    Aw[(r0 + 8) * 180 + c2] = *(uint32_t*)&p23;
                    acc[mt][nt][0] = 0.f; acc[mt][nt][1] = 0.f;
                    acc[mt][nt][2] = 0.f; acc[mt][nt][3] = 0.f;
                }
            }
            __syncthreads();   // H visible to all warps
        }

        const int itk = (it < 11) ? it : it - 11;
        const uint32_t ringSlot = sb + SM_RING_B + slot * B_SLOT_B;
#pragma unroll
        for (int ks = 0; ks < 2; ++ks) {
            const uint32_t kByte = (uint32_t)(itk * 64 + ks * 32);  // (itk*32+ks*16)*2
            uint32_t a0[4], a1[4];
            ldsm_a4(a0, aLane + kByte);
            ldsm_a4(a1, aLane + 11520 + kByte);          // +16 rows * 720 B
            const uint32_t bBase = ringSlot + bLane + ks * 11520;
#pragma unroll
            for (int pr = 0; pr < 5; ++pr) {
                uint32_t bf[4];
                ldsm_bt4(bf, bBase + pr * 32);
                mma_fp16(acc[0][2 * pr],     a0, bf[0], bf[1]);
                mma_fp16(acc[1][2 * pr],     a1, bf[0], bf[1]);
                mma_fp16(acc[0][2 * pr + 1], a0, bf[2], bf[3]);
                mma_fp16(acc[1][2 * pr + 1], a1, bf[2], bf[3]);
            }
            {
                uint32_t c0, c1;
                ldsm_bt2(c0, c1, ringSlot + bLaneX2 + ks * 11520);
                mma_fp16(acc[0][10], a0, c0, c1);
                mma_fp16(acc[1][10], a1, c0, c1);
            }
        }

        // per-warp release of this slot (replaces block-wide __syncthreads)
        if (lane == 0) MBARRIER_ARRIVE(sb + SM_MBAR + 16 + 8 * slot);

        // producer: refill this slot with tile it+2 once all 8 warps released it
        if (tid == 0 && it < 20) {
            MBARRIER_WAIT_PARITY(sb + SM_MBAR + 16 + 8 * slot, (it >> 1) & 1);
            MBARRIER_EXPECT_TX(sb + SM_MBAR + 8 * slot, B_SLOT_B);
            BULK_G2S(sb + SM_RING_B + slot * B_SLOT_B, g_wpad + (size_t)(it + 2) * 11520,
                     B_SLOT_B, sb + SM_MBAR + 8 * slot);
        }
    }

    // epilogue 2: G = D2 + b2 (f32) overlays A + ring (all reads done)
    __syncthreads();
#pragma unroll
    for (int mt = 0; mt < 2; mt++) {
        int r0 = wm * 32 + mt * 16 + q;
#pragma unroll
        for (int nt = 0; nt < 11; nt++) {
            int c = wn * 88 + nt * 8 + 2 * kq;
            float* G0 = smf + SM_G_F + r0 * 356;
            float* G1 = smf + SM_G_F + (r0 + 8) * 356;
            *(float2*)&G0[c] = make_float2(acc[mt][nt][0] + smf[352 + c],
                                           acc[mt][nt][1] + smf[352 + c + 1]);
            *(float2*)&G1[c] = make_float2(acc[mt][nt][2] + smf[352 + c],
                                           acc[mt][nt][3] + smf[352 + c + 1]);
        }
    }
    __syncthreads();

    // final epilogue: coalesced gated outputs (608 cols = 152 float4 per row)
#pragma unroll 1
    for (int i = tid; i < 64 * 152; i += 256) {
        int rr = i / 152, seg = i % 152;
        int gr = rowBase + rr;
        if (gr >= N) continue;
        int oc = seg * 4;
        const float4 st = *(const float4*)&smf[SM_STATS_F + rr * 4]; // m0,r0,r1,r2
        const float* G = smf + SM_G_F + rr * 356;
        float4 o;
        if (oc < 128) {
            float4 x = *(const float4*)&nsc[(size_t)gr * NODE_DIM + oc];
            const float4 g4 = *(const float4*)&G[oc];
            o.x = x.x + g4.x; o.y = x.y + g4.y; o.z = x.z + g4.z; o.w = x.w + g4.w;
        } else if (oc < 256) {
            int gi = oc - 128;
            float4 ne = *(const float4*)&neq[(size_t)gr * EQUI_DIM + gi];
            const float4 g4 = *(const float4*)&G[oc];
            o.x = ne.x + (ne.x - st.x) * st.y * g4.x;
            o.y = ne.y + (ne.y - st.x) * st.y * g4.y;
            o.z = ne.z + (ne.z - st.x) * st.y * g4.z;
            o.w = ne.w + (ne.w - st.x) * st.y * g4.w;
        } else if (oc < 448) {
            int pos = oc - 256;
            float4 ne = *(const float4*)&neq[(size_t)gr * EQUI_DIM + 128 + pos];
            o.x = ne.x * (1.f + st.z * G[256 + (pos    ) / 3]);
            o.y = ne.y * (1.f + st.z * G[256 + (pos + 1) / 3]);
            o.z = ne.z * (1.f + st.z * G[256 + (pos + 2) / 3]);
            o.w = ne.w * (1.f + st.z * G[256 + (pos + 3) / 3]);
        } else {
            int pos = oc - 448;
            float4 ne = *(const float4*)&neq[(size_t)gr * EQUI_DIM + 320 + pos];
            o.x = ne.x * (1.f + st.w * G[320 + (pos    ) / 5]);
            o.y = ne.y * (1.f + st.w * G[320 + (pos + 1) / 5]);
            o.z = ne.z * (1.f + st.w * G[320 + (pos + 2) / 5]);
            o.w = ne.w * (1.f + st.w * G[320 + (pos + 3) / 5]);
        }
        *(float4*)&out[(size_t)gr * OUT_DIM + oc] = o;
    }
}

// ---------------------------------------------------------------------------
// Launcher
// ---------------------------------------------------------------------------
extern "C" void kernel_launch(void* const* d_in, const int* in_sizes, int n_in,
                              void* d_out, int out_size)
{
    const float* nsc = (const float*)d_in[0];
    const float* neq = (const float*)d_in[1];
    const float* lnw = (const float*)d_in[2];
    const float* lnb = (const float*)d_in[3];
    const float* W1  = (const float*)d_in[4];
    const float* b1  = (const float*)d_in[5];
    const float* W2  = (const float*)d_in[6];
    const float* b2  = (const float*)d_in[7];
    float* out = (float*)d_out;

    int N = in_sizes[0] / NODE_DIM;

    cudaFuncSetAttribute(mlp_kernel, cudaFuncAttributeMaxDynamicSharedMemorySize, SMEM_TOTAL);

    pack_kernel<<<176, 256>>>(W1, W2);

    int ctas = (N + 63) / 64;
    mlp_kernel<<<ctas, 256, SMEM_TOTAL>>>(b1, b2, lnw, lnb, nsc, neq, out, N);
}

// round 12
// speedup vs baseline: 1.0279x; 1.0279x over previous
#include <cuda_runtime.h>
#include <cuda_fp16.h>
#include <cstdint>

// ---------------------------------------------------------------------------
// Problem constants
// ---------------------------------------------------------------------------
#define NROWS_MAX 100000
#define CONCAT    352
#define NODE_DIM  128
#define EQUI_DIM  480
#define OUT_DIM   608

// Packed weights: 44 tiles (22 W1 + 22 W2); tile = 16 k-rows x 360 fp16
// (row stride 720 B, n-contiguous) = 11520 B.
__device__ __half g_wpad[(size_t)44 * 16 * 360];

// ---------------------------------------------------------------------------
// PTX helpers (sm_90-era baseline only; tcgen05 rejected by this toolchain)
// ---------------------------------------------------------------------------
__device__ __forceinline__ uint32_t smem_to_u32(const void* p) {
    uint32_t a;
    asm("{ .reg .u64 t; cvta.to.shared.u64 t, %1; cvt.u32.u64 %0, t; }" : "=r"(a) : "l"(p));
    return a;
}

__device__ __forceinline__ void mma_fp16(float* d, const uint32_t* a, uint32_t b0, uint32_t b1) {
    asm volatile(
        "mma.sync.aligned.m16n8k16.row.col.f32.f16.f16.f32 "
        "{%0,%1,%2,%3}, {%4,%5,%6,%7}, {%8,%9}, {%0,%1,%2,%3};\n"
        : "+f"(d[0]), "+f"(d[1]), "+f"(d[2]), "+f"(d[3])
        : "r"(a[0]), "r"(a[1]), "r"(a[2]), "r"(a[3]), "r"(b0), "r"(b1));
}

__device__ __forceinline__ void ldsm_a4(uint32_t* r, uint32_t addr) {
    asm volatile("ldmatrix.sync.aligned.m8n8.x4.shared.b16 {%0,%1,%2,%3}, [%4];"
        : "=r"(r[0]), "=r"(r[1]), "=r"(r[2]), "=r"(r[3]) : "r"(addr));
}
__device__ __forceinline__ void ldsm_bt4(uint32_t* r, uint32_t addr) {
    asm volatile("ldmatrix.sync.aligned.m8n8.x4.trans.shared.b16 {%0,%1,%2,%3}, [%4];"
        : "=r"(r[0]), "=r"(r[1]), "=r"(r[2]), "=r"(r[3]) : "r"(addr));
}
__device__ __forceinline__ void ldsm_bt2(uint32_t& r0, uint32_t& r1, uint32_t addr) {
    asm volatile("ldmatrix.sync.aligned.m8n8.x2.trans.shared.b16 {%0,%1}, [%2];"
        : "=r"(r0), "=r"(r1) : "r"(addr));
}

#define MBARRIER_INIT(addr, cnt) \
    asm volatile("mbarrier.init.shared.b64 [%0], %1;" :: "r"((uint32_t)(addr)), "r"((uint32_t)(cnt)) : "memory")

#define MBARRIER_EXPECT_TX(addr, bytes) \
    asm volatile("mbarrier.arrive.expect_tx.shared.b64 _, [%0], %1;" \
                 :: "r"((uint32_t)(addr)), "r"((uint32_t)(bytes)) : "memory")

#define MBARRIER_ARRIVE(addr) \
    asm volatile("mbarrier.arrive.shared.b64 _, [%0];" :: "r"((uint32_t)(addr)) : "memory")

#define BULK_G2S(dst, src, bytes, mbar) \
    asm volatile("cp.async.bulk.shared::cluster.global.mbarrier::complete_tx::bytes [%0], [%1], %2, [%3];" \
                 :: "r"((uint32_t)(dst)), "l"(src), "r"((uint32_t)(bytes)), "r"((uint32_t)(mbar)) : "memory")

#define MBARRIER_WAIT_PARITY(mbar_smem_addr, phase_parity) do { \
    uint32_t _mbar = (uint32_t)(mbar_smem_addr); \
    uint32_t _parity = (uint32_t)(phase_parity); \
    uint32_t _done; \
    asm volatile( \
        "{\n\t.reg .pred p;\n\t" \
        "mbarrier.try_wait.parity.acquire.cta.shared::cta.b64 p, [%1], %2;\n\t" \
        "selp.b32 %0, 1, 0, p;\n\t}" \
        : "=r"(_done) : "r"(_mbar), "r"(_parity) : "memory"); \
    if (!_done) { \
        asm volatile( \
            "{\n\t.reg .pred P1;\n\t" \
            "WAIT_LOOP_%=:\n\t" \
            "mbarrier.try_wait.parity.acquire.cta.shared::cta.b64 P1, [%0], %1, 0x989680;\n\t" \
            "@P1 bra.uni WAIT_DONE_%=;\n\t" \
            "bra.uni WAIT_LOOP_%=;\n\t" \
            "WAIT_DONE_%=:\n\t}" \
            :: "r"(_mbar), "r"(_parity) : "memory"); \
    } \
} while(0)

// ---------------------------------------------------------------------------
// Kernel 0: pack W1/W2 -> g_wpad as plain fp16 rows [k][n], stride 360 halves.
// 176 blocks: tile j = b/4, part p = b%4 (4 k-rows per block).
// ---------------------------------------------------------------------------
__global__ void pack_kernel(const float* __restrict__ W1, const float* __restrict__ W2) {
    int b = blockIdx.x;
    int j = b >> 2, p = b & 3;
    const float* src = (j < 22) ? (W1 + (size_t)j * 16 * CONCAT)
                                : (W2 + (size_t)(j - 22) * 16 * CONCAT);
    __half* dst = g_wpad + (size_t)j * 16 * 360;
    for (int i = threadIdx.x; i < 4 * CONCAT; i += 256) {
        int k = p * 4 + i / CONCAT, n = i % CONCAT;
        dst[k * 360 + n] = __float2half_rn(src[(size_t)k * CONCAT + n]);
    }
}

// ---------------------------------------------------------------------------
// Fused kernel: norm prologue + MLP + gated epilogue.
// 64-row CTAs, 256 threads (8 warps, 2M x 4N, warp tile 32x88), 2 CTAs/SM.
// A (64x352 fp16, row stride 720 B) built in smem by the norm prologue;
// B streamed as K=16 tiles via 4-deep bulk ring with full/free mbarriers;
// slots released right after the last ldmatrix (fragments in regs).
//
// smem bytes:
//   bias  @0     : 704 f32             (2816)
//   stats @2816  : 64*4 f32            (1024)  -> 3840
//   A     @3840  : 64*180 words        (46080) -> 49920
//   ring  @49920 : 4*16*360 halves     (46080) -> 96000
//   mbars @96000 : full0..3, free0..3  (64)    -> 96064
//   G overlay @3840 : 64*356 f32       (91136) -> 94976 (post-loop, safe)
// total 96064 B/CTA -> 2 CTAs/SM
// ---------------------------------------------------------------------------
#define SM_STATS_F 704
#define SM_A_B     3840
#define SM_RING_B  49920
#define SM_MBAR    96000
#define SMEM_TOTAL 96064
#define B_SLOT_B   11520
#define SM_G_F     960          // float index of G overlay (3840/4)

#define MMA4(pr, bf) do { \
    mma_fp16(acc[0][2*(pr)],     a0, (bf)[0], (bf)[1]); \
    mma_fp16(acc[1][2*(pr)],     a1, (bf)[0], (bf)[1]); \
    mma_fp16(acc[0][2*(pr) + 1], a0, (bf)[2], (bf)[3]); \
    mma_fp16(acc[1][2*(pr) + 1], a1, (bf)[2], (bf)[3]); \
} while (0)

__global__ __launch_bounds__(256, 2) void mlp_kernel(
    const float* __restrict__ b1, const float* __restrict__ b2,
    const float* __restrict__ lnw, const float* __restrict__ lnb,
    const float* __restrict__ nsc, const float* __restrict__ neq,
    float* __restrict__ out, int N)
{
    extern __shared__ char smc[];
    float* smf = (float*)smc;
    uint32_t sb = smem_to_u32(smc);
    const int tid = threadIdx.x, lane = tid & 31, wid = tid >> 5;
    const int wm = wid >> 2, wn = wid & 3;          // 2 x 4 warp grid
    const int rowBase = blockIdx.x * 64;

    uint32_t* Aw = (uint32_t*)(smc + SM_A_B);

    if (tid == 0) {
#pragma unroll
        for (int s = 0; s < 4; ++s) {
            MBARRIER_INIT(sb + SM_MBAR + 8 * s, 1);        // full_s
            MBARRIER_INIT(sb + SM_MBAR + 32 + 8 * s, 8);   // free_s
        }
    }
    for (int i = tid; i < 704; i += 256)
        smf[i] = (i < CONCAT) ? b1[i] : b2[i - CONCAT];
    __syncthreads();

    // producer: prefetch B tiles 0..3 into slots 0..3
    if (tid == 0) {
#pragma unroll
        for (int s = 0; s < 4; ++s) {
            MBARRIER_EXPECT_TX(sb + SM_MBAR + 8 * s, B_SLOT_B);
            BULK_G2S(sb + SM_RING_B + s * B_SLOT_B, g_wpad + (size_t)s * 5760,
                     B_SLOT_B, sb + SM_MBAR + 8 * s);
        }
    }

    // ---------------- norm prologue: 8 rows per warp ----------------
    {
        const float4 lw4 = *(const float4*)&lnw[lane * 4];
        const float4 lb4 = *(const float4*)&lnb[lane * 4];
#pragma unroll 2
        for (int pass = 0; pass < 8; ++pass) {
            int rr = wid * 8 + pass;
            int gr = rowBase + rr;
            float4 xv = make_float4(0.f, 0.f, 0.f, 0.f);
            float4 ev = make_float4(0.f, 0.f, 0.f, 0.f);
            float a0 = 0.f, a1 = 0.f, a2 = 0.f, a3 = 0.f, a4 = 0.f, a5 = 0.f;
            float q0 = 0.f, q1 = 0.f, q2 = 0.f, q3 = 0.f, q4 = 0.f;
            if (gr < N) {
                const float* xs = nsc + (size_t)gr * NODE_DIM;
                const float* xe = neq + (size_t)gr * EQUI_DIM;
                xv = *(const float4*)&xs[lane * 4];
                ev = *(const float4*)&xe[lane * 4];
                const float* l1p = &xe[128 + 6 * lane];
                a0 = l1p[0]; a1 = l1p[1]; a2 = l1p[2];
                a3 = l1p[3]; a4 = l1p[4]; a5 = l1p[5];
                const float* l2p = &xe[320 + 5 * lane];
                q0 = l2p[0]; q1 = l2p[1]; q2 = l2p[2]; q3 = l2p[3]; q4 = l2p[4];
            }
            float s1a = a0 * a0 + a1 * a1 + a2 * a2;
            float s1b = a3 * a3 + a4 * a4 + a5 * a5;
            float s2  = q0 * q0 + q1 * q1 + q2 * q2 + q3 * q3 + q4 * q4;

            float sx  = xv.x + xv.y + xv.z + xv.w;
            float sxx = xv.x * xv.x + xv.y * xv.y + xv.z * xv.z + xv.w * xv.w;
            float se  = ev.x + ev.y + ev.z + ev.w;
            float se2 = ev.x * ev.x + ev.y * ev.y + ev.z * ev.z + ev.w * ev.w;
            float ssl1 = s1a + s1b;
            float ssl2 = s2;
#pragma unroll
            for (int o = 16; o > 0; o >>= 1) {
                sx   += __shfl_xor_sync(~0u, sx, o);
                sxx  += __shfl_xor_sync(~0u, sxx, o);
                se   += __shfl_xor_sync(~0u, se, o);
                se2  += __shfl_xor_sync(~0u, se2, o);
                ssl1 += __shfl_xor_sync(~0u, ssl1, o);
                ssl2 += __shfl_xor_sync(~0u, ssl2, o);
            }
            float mu  = sx * (1.f / 128.f);
            float var = sxx * (1.f / 128.f) - mu * mu;
            float rs  = rsqrtf(var + 1e-5f);
            float m0  = se * (1.f / 128.f);
            float sc2m = se2 * (1.f / 128.f) - m0 * m0;
            float r0 = rsqrtf(sc2m + 1e-5f);
            float r1 = rsqrtf(ssl1 * (1.f / 64.f) + 1e-5f);
            float r2 = rsqrtf(ssl2 * (1.f / 32.f) + 1e-5f);

            uint32_t* Arow = Aw + rr * 180;
            {
                float f0 = (xv.x - mu) * rs * lw4.x + lb4.x;
                float f1 = (xv.y - mu) * rs * lw4.y + lb4.y;
                float f2 = (xv.z - mu) * rs * lw4.z + lb4.z;
                float f3 = (xv.w - mu) * rs * lw4.w + lb4.w;
                __half2 p0 = __floats2half2_rn(f0, f1);
                __half2 p1 = __floats2half2_rn(f2, f3);
                Arow[lane * 2] = *(uint32_t*)&p0;
                Arow[lane * 2 + 1] = *(uint32_t*)&p1;
            }
            {
                float g0 = (ev.x - m0) * r0, g1 = (ev.y - m0) * r0;
                float g2 = (ev.z - m0) * r0, g3 = (ev.w - m0) * r0;
                __half2 p0 = __floats2half2_rn(g0 * g0, g1 * g1);
                __half2 p1 = __floats2half2_rn(g2 * g2, g3 * g3);
                Arow[64 + lane * 2] = *(uint32_t*)&p0;
                Arow[64 + lane * 2 + 1] = *(uint32_t*)&p1;
            }
            {
                float v0 = s1a * r1 * r1 * 0.57735026918962576451f;
                float v1 = s1b * r1 * r1 * 0.57735026918962576451f;
                __half2 p = __floats2half2_rn(v0, v1);
                Arow[128 + lane] = *(uint32_t*)&p;
            }
            {
                float v = s2 * r2 * r2 * 0.44721359549995793928f;
                float vhi = __shfl_down_sync(~0u, v, 1);
                if (!(lane & 1)) {
                    __half2 p = __floats2half2_rn(v, vhi);
                    Arow[160 + (lane >> 1)] = *(uint32_t*)&p;
                }
            }
            if (lane == 0)
                *(float4*)&smf[SM_STATS_F + rr * 4] = make_float4(m0, r0, r1, r2);
        }
    }
    __syncthreads();   // A tile + stats complete

    float acc[2][11][4];
#pragma unroll
    for (int mt = 0; mt < 2; mt++)
#pragma unroll
        for (int nt = 0; nt < 11; nt++)
#pragma unroll
            for (int e = 0; e < 4; e++) acc[mt][nt][e] = 0.f;

    // ldmatrix lane addresses (g8 = lane/8, l8 = lane%8)
    const int g8 = lane >> 3, l8 = lane & 7;
    const uint32_t aLane = sb + SM_A_B +
        (uint32_t)((wm * 32 + (g8 & 1) * 8 + l8) * 720 + (g8 >> 1) * 16);
    const uint32_t bLane = (uint32_t)(((g8 & 1) * 8 + l8) * 720 + (g8 >> 1) * 16 + wn * 176);
    const uint32_t bLaneX2 = (uint32_t)(((g8 & 1) * 8 + l8) * 720 + wn * 176 + 160);

    // 44 iterations of K=16: 0..21 = GEMM1 (W1), 22..43 = GEMM2 (W2)
#pragma unroll 1
    for (int it = 0; it < 44; ++it) {
        const int slot = it & 3;
        const int par  = (it >> 2) & 1;
        MBARRIER_WAIT_PARITY(sb + SM_MBAR + 8 * slot, par);

        if (it == 22) {
            // epilogue 1: H = fp16(silu(D1 + b1)) overwrites A in place.
            __syncthreads();   // all warps done reading A for GEMM1
            const int q = lane >> 2, kq = lane & 3;
#pragma unroll
            for (int mt = 0; mt < 2; mt++) {
                int r0 = wm * 32 + mt * 16 + q;
#pragma unroll
                for (int nt = 0; nt < 11; nt++) {
                    int c = wn * 88 + nt * 8 + 2 * kq;
                    int c2 = c >> 1;
                    float h0 = acc[mt][nt][0] + smf[c];
                    float h1 = acc[mt][nt][1] + smf[c + 1];
                    float h2 = acc[mt][nt][2] + smf[c];
                    float h3 = acc[mt][nt][3] + smf[c + 1];
                    h0 = __fdividef(h0, 1.f + __expf(-h0));
                    h1 = __fdividef(h1, 1.f + __expf(-h1));
                    h2 = __fdividef(h2, 1.f + __expf(-h2));
                    h3 = __fdividef(h3, 1.f + __expf(-h3));
                    __half2 p01 = __floats2half2_rn(h0, h1);
                    __half2 p23 = __floats2half2_rn(h2, h3);
                    Aw[r0 * 180 + c2] = *(uint32_t*)&p01;
                    Aw[(r0 + 8) * 180 + c2] = *(uint32_t*)&p23;
                    acc[mt][nt][0] = 0.f; acc[mt][nt][1] = 0.f;
                    acc[mt][nt][2] = 0.f; acc[mt][nt][3] = 0.f;
                }
            }
            __syncthreads();   // H visible to all warps
        }

        const int itk = (it < 22) ? it : it - 22;
        const uint32_t ringSlot = sb + SM_RING_B + slot * B_SLOT_B;
        uint32_t a0[4], a1[4], bA[4], bB[4], c0, c1;
        ldsm_a4(a0, aLane + itk * 32);
        ldsm_a4(a1, aLane + 11520 + itk * 32);           // +16 rows * 720 B
        ldsm_bt2(c0, c1, ringSlot + bLaneX2);
        ldsm_bt4(bA, ringSlot + bLane);
        ldsm_bt4(bB, ringSlot + bLane + 32);
        MMA4(0, bA);
        ldsm_bt4(bA, ringSlot + bLane + 64);
        MMA4(1, bB);
        ldsm_bt4(bB, ringSlot + bLane + 96);
        MMA4(2, bA);
        ldsm_bt4(bA, ringSlot + bLane + 128);
        // all reads of this slot issued -> release it (fragments in registers)
        if (lane == 0) MBARRIER_ARRIVE(sb + SM_MBAR + 32 + 8 * slot);
        MMA4(3, bB);
        MMA4(4, bA);
        mma_fp16(acc[0][10], a0, c0, c1);
        mma_fp16(acc[1][10], a1, c0, c1);

        // producer: refill this slot with tile it+4 once all 8 warps released it
        if (tid == 0 && it < 40) {
            MBARRIER_WAIT_PARITY(sb + SM_MBAR + 32 + 8 * slot, par);
            MBARRIER_EXPECT_TX(sb + SM_MBAR + 8 * slot, B_SLOT_B);
            BULK_G2S(sb + SM_RING_B + slot * B_SLOT_B, g_wpad + (size_t)(it + 4) * 5760,
                     B_SLOT_B, sb + SM_MBAR + 8 * slot);
        }
    }

    // epilogue 2: G = D2 + b2 (f32) overlays A + ring (all reads done)
    __syncthreads();
    {
        const int q = lane >> 2, kq = lane & 3;
#pragma unroll
        for (int mt = 0; mt < 2; mt++) {
            int r0 = wm * 32 + mt * 16 + q;
#pragma unroll
            for (int nt = 0; nt < 11; nt++) {
                int c = wn * 88 + nt * 8 + 2 * kq;
                float* G0 = smf + SM_G_F + r0 * 356;
                float* G1 = smf + SM_G_F + (r0 + 8) * 356;
                *(float2*)&G0[c] = make_float2(acc[mt][nt][0] + smf[352 + c],
                                               acc[mt][nt][1] + smf[352 + c + 1]);
                *(float2*)&G1[c] = make_float2(acc[mt][nt][2] + smf[352 + c],
                                               acc[mt][nt][3] + smf[352 + c + 1]);
            }
        }
    }
    __syncthreads();

    // final epilogue: coalesced gated outputs (608 cols = 152 float4 per row)
    // 64*152 = 9728 = 38 * 256 exactly.
#pragma unroll 2
    for (int j = 0; j < 38; ++j) {
        int i = j * 256 + tid;
        int rr = i / 152, seg = i % 152;
        int gr = rowBase + rr;
        if (gr >= N) continue;
        int oc = seg * 4;
        const float4 st = *(const float4*)&smf[SM_STATS_F + rr * 4]; // m0,r0,r1,r2
        const float* G = smf + SM_G_F + rr * 356;
        float4 o;
        if (oc < 128) {
            float4 x = *(const float4*)&nsc[(size_t)gr * NODE_DIM + oc];
            const float4 g4 = *(const float4*)&G[oc];
            o.x = x.x + g4.x; o.y = x.y + g4.y; o.z = x.z + g4.z; o.w = x.w + g4.w;
        } else if (oc < 256) {
            int gi = oc - 128;
            float4 ne = *(const float4*)&neq[(size_t)gr * EQUI_DIM + gi];
            const float4 g4 = *(const float4*)&G[oc];
            o.x = ne.x + (ne.x - st.x) * st.y * g4.x;
            o.y = ne.y + (ne.y - st.x) * st.y * g4.y;
            o.z = ne.z + (ne.z - st.x) * st.y * g4.z;
            o.w = ne.w + (ne.w - st.x) * st.y * g4.w;
        } else if (oc < 448) {
            int pos = oc - 256;
            float4 ne = *(const float4*)&neq[(size_t)gr * EQUI_DIM + 128 + pos];
            o.x = ne.x * (1.f + st.z * G[256 + (pos    ) / 3]);
            o.y = ne.y * (1.f + st.z * G[256 + (pos + 1) / 3]);
            o.z = ne.z * (1.f + st.z * G[256 + (pos + 2) / 3]);
            o.w = ne.w * (1.f + st.z * G[256 + (pos + 3) / 3]);
        } else {
            int pos = oc - 448;
            float4 ne = *(const float4*)&neq[(size_t)gr * EQUI_DIM + 320 + pos];
            o.x = ne.x * (1.f + st.w * G[320 + (pos    ) / 5]);
            o.y = ne.y * (1.f + st.w * G[320 + (pos + 1) / 5]);
            o.z = ne.z * (1.f + st.w * G[320 + (pos + 2) / 5]);
            o.w = ne.w * (1.f + st.w * G[320 + (pos + 3) / 5]);
        }
        *(float4*)&out[(size_t)gr * OUT_DIM + oc] = o;
    }
}

// ---------------------------------------------------------------------------
// Launcher
// ---------------------------------------------------------------------------
extern "C" void kernel_launch(void* const* d_in, const int* in_sizes, int n_in,
                              void* d_out, int out_size)
{
    const float* nsc = (const float*)d_in[0];
    const float* neq = (const float*)d_in[1];
    const float* lnw = (const float*)d_in[2];
    const float* lnb = (const float*)d_in[3];
    const float* W1  = (const float*)d_in[4];
    const float* b1  = (const float*)d_in[5];
    const float* W2  = (const float*)d_in[6];
    const float* b2  = (const float*)d_in[7];
    float* out = (float*)d_out;

    int N = in_sizes[0] / NODE_DIM;

    cudaFuncSetAttribute(mlp_kernel, cudaFuncAttributeMaxDynamicSharedMemorySize, SMEM_TOTAL);

    pack_kernel<<<176, 256>>>(W1, W2);

    int ctas = (N + 63) / 64;
    mlp_kernel<<<ctas, 256, SMEM_TOTAL>>>(b1, b2, lnw, lnb, nsc, neq, out, N);
}